// round 3
// baseline (speedup 1.0000x reference)
#include <cuda_runtime.h>
#include <math.h>

#define NBLK 64
#define NTHR 256

#define NB 2
#define NF 32
#define ND 512
#define NH 8
#define NHD 64
#define NFF 2048
#define NL 4
#define NM 256

// ---------------- persistent device state (no allocs) ----------------
__device__ float g_K [NL][NB][NF][ND];
__device__ float g_Vo[NL][NB][NF][NH][ND];   // per-head v @ Wo_h (8 MB)
__device__ float g_Vt[NL][NB][NF][ND];
__device__ float g_CA[NL][NB][NF][ND];
__device__ float g_gb[NL * 3][NB][2 * ND];
__device__ float g_ppe[NF][ND];
__device__ float g_x0[NB][ND];
__device__ float g_q [NB][ND];
__device__ float g_v [NB][ND];
__device__ float g_att[NB][NH][NF];
__device__ float g_y1[NB][ND];
__device__ float g_x2[NB][ND];
__device__ float g_h [NB][NFF];
__device__ float g_y3[NB][ND];

__device__ unsigned g_barcnt = 0;
__device__ unsigned g_bargen = 0;

struct Smem {
    float x[4096];
    float x2[512];
    float red[32];
    float red2[8][32][2];
};

// ---------------- grid barrier (all NBLK blocks co-resident) ----------------
__device__ __forceinline__ void gsync() {
    __threadfence();              // release: my global writes visible in L2
    __syncthreads();
    if (threadIdx.x == 0) {
        unsigned gen = atomicAdd(&g_bargen, 0u);
        if (atomicAdd(&g_barcnt, 1u) == (unsigned)(NBLK - 1)) {
            atomicSub(&g_barcnt, (unsigned)NBLK);   // commutes with next-epoch adds
            atomicAdd(&g_bargen, 1u);
        } else {
            while (atomicAdd(&g_bargen, 0u) == gen) { }
        }
        __threadfence();          // acquire: invalidate L1 before consumers read
    }
    __syncthreads();
}

// ---------------- block-wide style-adaptive layernorm on a 512-slice --------
// src/dst are shared 512-float slices (may alias). G = [gamma(512), beta(512)].
__device__ __forceinline__ void blk_saln(Smem& sm, const float* G,
                                         const float* src, float* dst,
                                         const float* addv) {
    int tid = threadIdx.x;
    float a0 = src[tid], a1 = src[tid + 256];
    float s = a0 + a1, q = a0 * a0 + a1 * a1;
#pragma unroll
    for (int o = 16; o; o >>= 1) {
        s += __shfl_xor_sync(0xffffffffu, s, o);
        q += __shfl_xor_sync(0xffffffffu, q, o);
    }
    if ((tid & 31) == 0) { sm.red[tid >> 5] = s; sm.red[8 + (tid >> 5)] = q; }
    __syncthreads();
    if (tid == 0) {
        float S = 0.f, Q = 0.f;
#pragma unroll
        for (int k = 0; k < 8; k++) { S += sm.red[k]; Q += sm.red[8 + k]; }
        float mu = S * (1.f / 512.f);
        sm.red[16] = mu;
        sm.red[17] = rsqrtf(Q * (1.f / 512.f) - mu * mu + 1e-5f);
    }
    __syncthreads();
    float mu = sm.red[16], rs = sm.red[17];
    float o0 = (a0 - mu) * rs * G[tid] + G[512 + tid];
    float o1 = (a1 - mu) * rs * G[tid + 256] + G[512 + tid + 256];
    if (addv) { o0 += addv[tid]; o1 += addv[tid + 256]; }
    __syncthreads();              // everyone done reading src before overwrite
    dst[tid] = o0; dst[tid + 256] = o1;
    __syncthreads();
}

// dual-batch GEMV tile: 32 cols, x = shared [2*K] (b0 then b1), W pre-offset by colbase.
template <int K>
__device__ __forceinline__ void gemv2(Smem& sm, const float* xx,
                                      const float* W, int ldw,
                                      float& out0, float& out1) {
    const int KC = K / 8;
    int c = threadIdx.x & 31, r = threadIdx.x >> 5;
    const float* Wp = W + (size_t)(r * KC) * ldw + c;
    float a0 = 0.f, a1 = 0.f;
#pragma unroll 8
    for (int e = 0; e < KC; e++) {
        float w = Wp[(size_t)e * ldw];
        a0 += xx[r * KC + e] * w;
        a1 += xx[K + r * KC + e] * w;
    }
    sm.red2[r][c][0] = a0; sm.red2[r][c][1] = a1;
    __syncthreads();
    if (r == 0) {
        float s0 = 0.f, s1 = 0.f;
#pragma unroll
        for (int k = 0; k < 8; k++) { s0 += sm.red2[k][c][0]; s1 += sm.red2[k][c][1]; }
        out0 = s0; out1 = s1;
    }
    __syncthreads();
}

// ---------------------------------------------------------------------------
__global__ __launch_bounds__(NTHR) void mega(
    const float* __restrict__ content, const float* __restrict__ style,
    const float* __restrict__ init_st,
    const float* __restrict__ motion_W, const float* __restrict__ motion_b,
    const float* __restrict__ motionr_W, const float* __restrict__ motionr_b,
    const float* __restrict__ sa_Wq, const float* __restrict__ sa_bq,
    const float* __restrict__ sa_Wk, const float* __restrict__ sa_bk,
    const float* __restrict__ sa_Wv, const float* __restrict__ sa_bv,
    const float* __restrict__ sa_Wo, const float* __restrict__ sa_bo,
    const float* __restrict__ ca_Wv, const float* __restrict__ ca_bv,
    const float* __restrict__ ca_Wo, const float* __restrict__ ca_bo,
    const float* __restrict__ ff_W1, const float* __restrict__ ff_b1,
    const float* __restrict__ ff_W2, const float* __restrict__ ff_b2,
    const float* __restrict__ saln_W, const float* __restrict__ saln_b,
    float* __restrict__ outp)
{
    __shared__ Smem sm;
    const int blk = blockIdx.x, tid = threadIdx.x;
    const int c = tid & 31, r = tid >> 5;

    // ================= P0: PPE + SALN gamma/beta + Vt = content@Wv+bv ========
    {
        int idx = blk * NTHR + tid;             // exactly NF*ND = 16384
        int f = idx >> 9, d = idx & 511;
        float divv = expf((float)(d & ~1) * (-9.210340371976184f / 512.0f));
        float a = (float)(f % 30) * divv;
        g_ppe[f][d] = (d & 1) ? cosf(a) : sinf(a);
    }
    for (int t = blk; t < 384; t += NBLK) {     // 12 ls * 32 coltiles
        int ls = t >> 5, colbase = (t & 31) * 32;
        for (int u = tid; u < 1024; u += NTHR) sm.x[u] = style[u];
        __syncthreads();
        float o0, o1;
        gemv2<512>(sm, sm.x, saln_W + (size_t)ls * 512 * 1024 + colbase, 1024, o0, o1);
        if (r == 0) {
            float bb = saln_b[ls * 1024 + colbase + c];
            g_gb[ls][0][colbase + c] = o0 + bb;
            g_gb[ls][1][colbase + c] = o1 + bb;
        }
        __syncthreads();
    }
    for (int t = blk; t < 512; t += NBLK) {     // 4 l * 16 coltiles * 8 rowgroups
        int l = t >> 7, colt = (t >> 3) & 15, rg = t & 7;
        int colbase = colt * 32;
        for (int u = tid; u < 4096; u += NTHR)
            sm.x[u] = content[(size_t)(rg * 8) * 512 + u];
        __syncthreads();
        const float* Wp = ca_Wv + (size_t)l * 512 * 512 + (size_t)(r * 64) * 512 + colbase + c;
        float acc[8];
#pragma unroll
        for (int rr = 0; rr < 8; rr++) acc[rr] = 0.f;
#pragma unroll 8
        for (int e = 0; e < 64; e++) {
            float w = Wp[(size_t)e * 512];
#pragma unroll
            for (int rr = 0; rr < 8; rr++) acc[rr] += sm.x[rr * 512 + r * 64 + e] * w;
        }
        for (int rr = 0; rr < 8; rr++) {
            sm.red2[r][c][0] = acc[rr];
            __syncthreads();
            if (r == 0) {
                float s = 0.f;
#pragma unroll
                for (int k = 0; k < 8; k++) s += sm.red2[k][c][0];
                int row = rg * 8 + rr;
                g_Vt[l][row >> 5][row & 31][colbase + c] = s + ca_bv[l * 512 + colbase + c];
            }
            __syncthreads();
        }
    }
    gsync();

    // ================= P1: CA = Vt@Wo+bo  and  emb0 ==========================
    for (int t = blk; t < 512; t += NBLK) {
        int l = t >> 7, colt = (t >> 3) & 15, rg = t & 7;
        int colbase = colt * 32;
        const float* vt = &g_Vt[l][0][0][0];
        for (int u = tid; u < 4096; u += NTHR)
            sm.x[u] = vt[(size_t)(rg * 8) * 512 + u];
        __syncthreads();
        const float* Wp = ca_Wo + (size_t)l * 512 * 512 + (size_t)(r * 64) * 512 + colbase + c;
        float acc[8];
#pragma unroll
        for (int rr = 0; rr < 8; rr++) acc[rr] = 0.f;
#pragma unroll 8
        for (int e = 0; e < 64; e++) {
            float w = Wp[(size_t)e * 512];
#pragma unroll
            for (int rr = 0; rr < 8; rr++) acc[rr] += sm.x[rr * 512 + r * 64 + e] * w;
        }
        for (int rr = 0; rr < 8; rr++) {
            sm.red2[r][c][0] = acc[rr];
            __syncthreads();
            if (r == 0) {
                float s = 0.f;
#pragma unroll
                for (int k = 0; k < 8; k++) s += sm.red2[k][c][0];
                int row = rg * 8 + rr;
                g_CA[l][row >> 5][row & 31][colbase + c] = s + ca_bo[l * 512 + colbase + c];
            }
            __syncthreads();
        }
    }
    if (blk < 16) {                              // emb0: x0 = init@Wm + bm + ppe[0]
        for (int u = tid; u < 512; u += NTHR) sm.x[u] = init_st[u];
        __syncthreads();
        float o0, o1;
        gemv2<256>(sm, sm.x, motion_W + blk * 32, 512, o0, o1);
        if (r == 0) {
            int col = blk * 32 + c;
            float ex = motion_b[col] + g_ppe[0][col];
            g_x0[0][col] = o0 + ex;
            g_x0[1][col] = o1 + ex;
        }
    }
    gsync();

    // ================= autoregressive decode =================================
    for (int i = 0; i < NF; i++) {
        for (int l = 0; l < NL; l++) {
            // ---- A: (saln3 of prev layer, redundant) + q/k/v GEMVs ----
            if (blk < 48) {
                if (l == 0) {
                    for (int u = tid; u < 1024; u += NTHR) sm.x[u] = ((const float*)g_x0)[u];
                    __syncthreads();
                } else {
                    for (int u = tid; u < 1024; u += NTHR) sm.x[u] = ((const float*)g_y3)[u];
                    __syncthreads();
                    blk_saln(sm, g_gb[(l - 1) * 3 + 2][0], sm.x, sm.x, 0);
                    blk_saln(sm, g_gb[(l - 1) * 3 + 2][1], sm.x + 512, sm.x + 512, 0);
                    if (blk == 0) {
                        float* x0f = (float*)g_x0;
                        x0f[tid] = sm.x[tid];         x0f[tid + 256] = sm.x[tid + 256];
                        x0f[tid + 512] = sm.x[tid + 512]; x0f[tid + 768] = sm.x[tid + 768];
                    }
                }
                int gcol = blk * 32;
                int which = gcol >> 9, colb = gcol & 511;
                const float* W = (which == 0 ? sa_Wq : which == 1 ? sa_Wk : sa_Wv)
                               + (size_t)l * 512 * 512 + colb;
                float o0, o1;
                gemv2<512>(sm, sm.x, W, 512, o0, o1);
                if (r == 0) {
                    const float* bias = which == 0 ? sa_bq : which == 1 ? sa_bk : sa_bv;
                    float bb = bias[l * 512 + colb + c];
                    o0 += bb; o1 += bb;
                    int cc = colb + c;
                    if (which == 0)      { g_q[0][cc] = o0;       g_q[1][cc] = o1; }
                    else if (which == 1) { g_K[l][0][i][cc] = o0; g_K[l][1][i][cc] = o1; }
                    else                 { g_v[0][cc] = o0;       g_v[1][cc] = o1; }
                }
            }
            gsync();

            // ---- B: Vo[h] = v_h @ Wo_h  +  attention scores/softmax ----
            for (int t = blk; t < 256; t += NBLK) {
                int colt = t & 15, h = (t >> 4) & 7, b = t >> 7;
                int colbase = colt * 32;
                if (tid < 64) sm.x[tid] = g_v[b][h * 64 + tid];
                __syncthreads();
                const float* Wp = sa_Wo + (size_t)l * 512 * 512
                                + (size_t)(h * 64 + r * 8) * 512 + colbase + c;
                float a = 0.f;
#pragma unroll
                for (int e = 0; e < 8; e++) a += sm.x[r * 8 + e] * Wp[(size_t)e * 512];
                sm.red2[r][c][0] = a;
                __syncthreads();
                if (r == 0) {
                    float s = 0.f;
#pragma unroll
                    for (int k = 0; k < 8; k++) s += sm.red2[k][c][0];
                    g_Vo[l][b][i][h][colbase + c] = s;
                }
                __syncthreads();
            }
            if (blk >= 62) {                    // scores for batch b = blk-62
                int b = blk - 62;
                for (int u = tid; u < 512; u += NTHR) sm.x[u] = g_q[b][u];
                __syncthreads();
                int h = r, j = c;               // warp = head, lane = key index
                float sc = -1e30f;
                if (j <= i) {
                    const float* kp = &g_K[l][b][j][h * 64];
                    float d = 0.f;
#pragma unroll
                    for (int e = 0; e < 64; e++) d += sm.x[h * 64 + e] * kp[e];
                    sc = d * 0.125f - exp2f(-(float)(h + 1)) * (float)((i - j) / 30);
                }
                float mx = sc;
#pragma unroll
                for (int o = 16; o; o >>= 1) mx = fmaxf(mx, __shfl_xor_sync(0xffffffffu, mx, o));
                float ev = (j <= i) ? expf(sc - mx) : 0.f;
                float smm = ev;
#pragma unroll
                for (int o = 16; o; o >>= 1) smm += __shfl_xor_sync(0xffffffffu, smm, o);
                g_att[b][h][j] = ev / smm;
            }
            gsync();

            // ---- C: y1 = sum_{j,h} att*Vo + bo + x0 ----
            if (blk < 32) {
                int b = blk & 1, dbase = (blk >> 1) * 32;
                for (int u = tid; u < 256; u += NTHR) sm.x2[u] = (&g_att[b][0][0])[u];
                __syncthreads();
                int d = dbase + c;
                int M = (i + 1) * 8;
                float a = 0.f;
                for (int m = r; m < M; m += 8) {     // h = r fixed, j varies
                    int j = m >> 3, h = m & 7;
                    a += sm.x2[h * 32 + j] * g_Vo[l][b][j][h][d];
                }
                sm.red2[r][c][0] = a;
                __syncthreads();
                if (r == 0) {
                    float s = 0.f;
#pragma unroll
                    for (int k = 0; k < 8; k++) s += sm.red2[k][c][0];
                    g_y1[b][d] = s + sa_bo[l * 512 + d] + g_x0[b][d];
                }
            }
            gsync();

            // ---- D: x2 = saln2(saln1(y1)+CA) (redundant per block) + FF1 ----
            {
                int b = blk & 1;
                for (int u = tid; u < 512; u += NTHR) sm.x[u] = g_y1[b][u];
                __syncthreads();
                blk_saln(sm, g_gb[l * 3 + 0][b], sm.x, sm.x2, &g_CA[l][b][i][0]);
                blk_saln(sm, g_gb[l * 3 + 1][b], sm.x2, sm.x, 0);
                if ((blk >> 1) == 0) {
                    g_x2[b][tid] = sm.x[tid];
                    g_x2[b][tid + 256] = sm.x[tid + 256];
                }
#pragma unroll
                for (int tt = 0; tt < 2; tt++) {
                    int colbase = ((blk >> 1) + tt * 32) * 32;
                    const float* Wp = ff_W1 + (size_t)l * 512 * 2048
                                    + (size_t)(r * 64) * 2048 + colbase + c;
                    float a = 0.f;
#pragma unroll 8
                    for (int e = 0; e < 64; e++) a += sm.x[r * 64 + e] * Wp[(size_t)e * 2048];
                    sm.red2[r][c][0] = a;
                    __syncthreads();
                    if (r == 0) {
                        float s = 0.f;
#pragma unroll
                        for (int k = 0; k < 8; k++) s += sm.red2[k][c][0];
                        g_h[b][colbase + c] = fmaxf(s + ff_b1[l * 2048 + colbase + c], 0.f);
                    }
                    __syncthreads();
                }
            }
            gsync();

            // ---- E: y3 = h@W2 + b2 + x2 ----
            {
                int b = blk & 1, colbase = (blk >> 1) * 16;
                for (int u = tid; u < 2048; u += NTHR) sm.x[u] = g_h[b][u];
                __syncthreads();
                int c16 = tid & 15, r16 = tid >> 4;
                const float* Wp = ff_W2 + (size_t)l * 2048 * 512
                                + (size_t)(r16 * 128) * 512 + colbase + c16;
                float a = 0.f;
#pragma unroll 8
                for (int e = 0; e < 128; e++) a += sm.x[r16 * 128 + e] * Wp[(size_t)e * 512];
                ((float*)sm.red2)[r16 * 16 + c16] = a;
                __syncthreads();
                if (tid < 16) {
                    float s = 0.f;
#pragma unroll
                    for (int k = 0; k < 16; k++) s += ((float*)sm.red2)[k * 16 + tid];
                    int col = colbase + tid;
                    g_y3[b][col] = s + ff_b2[l * 512 + col] + g_x2[b][col];
                }
            }
            gsync();
        } // layers

        // ---- OUT: row i = saln3(y3) @ motionr_W + br ----
        if (blk < 16) {
            int b = blk & 1, colbase = (blk >> 1) * 32;
            for (int u = tid; u < 512; u += NTHR) sm.x[u] = g_y3[b][u];
            __syncthreads();
            blk_saln(sm, g_gb[3 * 3 + 2][b], sm.x, sm.x, 0);
            const float* Wp = motionr_W + (size_t)(r * 64) * 256 + colbase + c;
            float a = 0.f;
#pragma unroll 8
            for (int e = 0; e < 64; e++) a += sm.x[r * 64 + e] * Wp[(size_t)e * 256];
            sm.red2[r][c][0] = a;
            __syncthreads();
            if (r == 0) {
                float s = 0.f;
#pragma unroll
                for (int k = 0; k < 8; k++) s += sm.red2[k][c][0];
                int col = colbase + c;
                outp[(size_t)b * NF * NM + (size_t)i * NM + col] = s + motionr_b[col];
            }
        }
        gsync();

        // ---- EMB: x0 = out_row @ motion_W + bm + ppe[i+1] ----
        if (i < NF - 1) {
            if (blk < 16) {
                for (int u = tid; u < 512; u += NTHR) {
                    int b = u >> 8, e = u & 255;
                    sm.x[u] = outp[(size_t)b * NF * NM + (size_t)i * NM + e];
                }
                __syncthreads();
                float o0, o1;
                gemv2<256>(sm, sm.x, motion_W + blk * 32, 512, o0, o1);
                if (r == 0) {
                    int col = blk * 32 + c;
                    float ex = motion_b[col] + g_ppe[i + 1][col];
                    g_x0[0][col] = o0 + ex;
                    g_x0[1][col] = o1 + ex;
                }
            }
            gsync();
        }
    } // steps
}

// ---------------------------------------------------------------------------
extern "C" void kernel_launch(void* const* d_in, const int* in_sizes, int n_in,
                              void* d_out, int out_size) {
    mega<<<NBLK, NTHR>>>(
        (const float*)d_in[0],  (const float*)d_in[1],  (const float*)d_in[2],
        (const float*)d_in[3],  (const float*)d_in[4],  (const float*)d_in[5],
        (const float*)d_in[6],
        (const float*)d_in[7],  (const float*)d_in[8],  (const float*)d_in[9],
        (const float*)d_in[10], (const float*)d_in[11], (const float*)d_in[12],
        (const float*)d_in[13], (const float*)d_in[14],
        /* ca_Wq/bq/Wk/bk (15-18) unused: one-hot cross-attn softmax */
        (const float*)d_in[19], (const float*)d_in[20], (const float*)d_in[21],
        (const float*)d_in[22],
        (const float*)d_in[23], (const float*)d_in[24], (const float*)d_in[25],
        (const float*)d_in[26],
        (const float*)d_in[27], (const float*)d_in[28],
        (float*)d_out);
    (void)in_sizes; (void)n_in; (void)out_size;
}